// round 12
// baseline (speedup 1.0000x reference)
#include <cuda_runtime.h>
#include <cstdint>

namespace {
constexpr int  CIN  = 16;
constexpr int  COUT = 16;
constexpr int  KS   = 4;
constexpr long long NN = 524288;
constexpr int  THREADS = 128;                 // 4 warps
constexpr int  TOK     = 128;                 // tokens per CTA-iter
constexpr int  TILES   = (int)(8 * NN / TOK); // 32768
constexpr int  GRID    = 8192;                // 4 tiles per CTA
constexpr int  PX      = 136;                 // u32 pitch, xh/xl rows (8cq+r banks)
}

__device__ __forceinline__ unsigned long long fma2(unsigned long long a,
                                                   unsigned long long b,
                                                   unsigned long long c) {
    unsigned long long d;
    asm("fma.rn.f32x2 %0, %1, %2, %3;" : "=l"(d) : "l"(a), "l"(b), "l"(c));
    return d;
}
__device__ __forceinline__ unsigned long long pack2(float lo, float hi) {
    unsigned long long d;
    asm("mov.b64 %0, {%1, %2};" : "=l"(d) : "f"(lo), "f"(hi));
    return d;
}
// pack two f32 -> bf16x2 rn. First operand = HIGH half (element 1).
__device__ __forceinline__ uint32_t packbf(float hi, float lo) {
    uint32_t r;
    asm("cvt.rn.bf16x2.f32 %0, %1, %2;" : "=r"(r) : "f"(hi), "f"(lo));
    return r;
}
// m16n8k16 row.col bf16 MMA, accumulate in place. A = weights (regs).
__device__ __forceinline__ void mma_bf16(float* d, const uint32_t* a,
                                         uint32_t b0, uint32_t b1) {
    asm volatile(
        "mma.sync.aligned.m16n8k16.row.col.f32.bf16.bf16.f32 "
        "{%0,%1,%2,%3}, {%4,%5,%6,%7}, {%8,%9}, {%0,%1,%2,%3};"
        : "+f"(d[0]), "+f"(d[1]), "+f"(d[2]), "+f"(d[3])
        : "r"(a[0]), "r"(a[1]), "r"(a[2]), "r"(a[3]), "r"(b0), "r"(b1));
}
__device__ __forceinline__ float u64lo(unsigned long long v) {
    return __uint_as_float((uint32_t)v);
}
__device__ __forceinline__ float u64hi(unsigned long long v) {
    return __uint_as_float((uint32_t)(v >> 32));
}

__global__ __launch_bounds__(THREADS, 5)
void tconv_mma_kernel(const float* __restrict__ inp,   // [B, CIN, N]
                      const float* __restrict__ wgt,   // [COUT, KS, CIN]
                      const float* __restrict__ att,   // [B, KS, N]
                      float* __restrict__ out)         // [B, COUT, N]
{
    // x pre-split into bf16 hi/lo channel-pairs (R11 layout). s: NO smem —
    // per-warp direct LDG + shuffle distribution.
    __shared__ __align__(16) uint32_t xh[2][8 * PX];
    __shared__ __align__(16) uint32_t xl[2][8 * PX];

    const int tid  = threadIdx.x;
    const int lane = tid & 31;
    const int w    = tid >> 5;
    const int cq   = lane & 3;
    const int r    = lane >> 2;
    const int c0   = tid >> 5;      // staging: pair-group
    const int q    = lane;          // staging: token slot
    const unsigned FULL = 0xFFFFFFFFu;

    // ---- W as A-fragments, built once (split hi/lo) ----
    uint32_t ah[KS][4], al[KS][4];
    #pragma unroll
    for (int kt = 0; kt < KS; kt++) {
        #pragma unroll
        for (int idx = 0; idx < 4; idx++) {
            int o  = r + 8 * (idx & 1);
            int cb = 2 * cq + 8 * (idx >> 1);
            float wa = wgt[(o * KS + kt) * CIN + cb];
            float wb = wgt[(o * KS + kt) * CIN + cb + 1];
            uint32_t hp = packbf(wb, wa);
            float ha = __uint_as_float(hp << 16);
            float hb = __uint_as_float(hp & 0xFFFF0000u);
            ah[kt][idx] = hp;
            al[kt][idx] = packbf(wb - hb, wa - ha);
        }
    }

    // ---- prologue: load tile 0 ----
    float2 ra[2][2], rb[2][2];
    float  sv[KS];                               // s for THIS warp's 32 tokens
    {
        int t = blockIdx.x;
        long long b = t >> 12, n0 = ((long long)(t & 4095) << 7);
        #pragma unroll
        for (int pp = 0; pp < 2; pp++) {
            int p = c0 + 4 * pp;
            #pragma unroll
            for (int g = 0; g < 2; g++) {
                long long tk = n0 + 64 * g + 2 * q;
                ra[pp][g] = *reinterpret_cast<const float2*>(inp + (b * CIN + 2 * p)     * NN + tk);
                rb[pp][g] = *reinterpret_cast<const float2*>(inp + (b * CIN + 2 * p + 1) * NN + tk);
            }
        }
        #pragma unroll
        for (int kt = 0; kt < KS; kt++)
            sv[kt] = att[(b * KS + kt) * NN + n0 + w * 32 + lane];
    }

    for (int i = 0; i < TILES / GRID; i++) {
        const int t = blockIdx.x + i * GRID;
        const int pbuf = i & 1;
        uint32_t* xhb = xh[pbuf];
        uint32_t* xlb = xl[pbuf];

        // ---- stage tile i: split x to bf16 hi/lo ----
        #pragma unroll
        for (int pp = 0; pp < 2; pp++) {
            int p = c0 + 4 * pp;
            #pragma unroll
            for (int g = 0; g < 2; g++) {
                int t0 = 64 * g + 2 * q;
                float a0 = ra[pp][g].x, b0 = rb[pp][g].x;
                float a1 = ra[pp][g].y, b1 = rb[pp][g].y;
                uint32_t h0 = packbf(b0, a0);
                uint32_t h1 = packbf(b1, a1);
                float f0lo = __uint_as_float(h0 << 16), f0hi = __uint_as_float(h0 & 0xFFFF0000u);
                float f1lo = __uint_as_float(h1 << 16), f1hi = __uint_as_float(h1 & 0xFFFF0000u);
                uint32_t l0 = packbf(b0 - f0hi, a0 - f0lo);
                uint32_t l1 = packbf(b1 - f1hi, a1 - f1lo);
                *reinterpret_cast<uint2*>(xhb + p * PX + t0) = make_uint2(h0, h1);
                *reinterpret_cast<uint2*>(xlb + p * PX + t0) = make_uint2(l0, l1);
            }
        }

        // prefetch tile i+1 (x and s) before the barrier
        float sn[KS];
        if (i + 1 < TILES / GRID) {
            int tn = t + GRID;
            long long b = tn >> 12, n0 = ((long long)(tn & 4095) << 7);
            #pragma unroll
            for (int pp = 0; pp < 2; pp++) {
                int p = c0 + 4 * pp;
                #pragma unroll
                for (int g = 0; g < 2; g++) {
                    long long tk = n0 + 64 * g + 2 * q;
                    ra[pp][g] = *reinterpret_cast<const float2*>(inp + (b * CIN + 2 * p)     * NN + tk);
                    rb[pp][g] = *reinterpret_cast<const float2*>(inp + (b * CIN + 2 * p + 1) * NN + tk);
                }
            }
            #pragma unroll
            for (int kt = 0; kt < KS; kt++)
                sn[kt] = att[(b * KS + kt) * NN + n0 + w * 32 + lane];
        }
        __syncthreads();

        const long long bb = t >> 12;
        const long long n0 = ((long long)(t & 4095) << 7);
        float* ob = out + bb * COUT * NN + n0;

        #pragma unroll
        for (int jp = 0; jp < 2; jp++) {
            const int tb0 = w * 32 + jp * 16;
            const int tb1 = tb0 + 8;
            unsigned long long yA0, yA1, yB0, yB1;

            // s token-pairs via shuffle (replaces smem s entirely):
            // tile A tokens: tb0+2cq, +1 -> local lanes jp*16+2cq, +1
            // tile B tokens: tb1+2cq, +1 -> local lanes jp*16+8+2cq, +1
            unsigned long long s2A[KS], s2B[KS];
            #pragma unroll
            for (int kt = 0; kt < KS; kt++) {
                float ax = __shfl_sync(FULL, sv[kt], jp * 16 + 2 * cq);
                float ay = __shfl_sync(FULL, sv[kt], jp * 16 + 2 * cq + 1);
                float bx = __shfl_sync(FULL, sv[kt], jp * 16 + 8 + 2 * cq);
                float by = __shfl_sync(FULL, sv[kt], jp * 16 + 8 + 2 * cq + 1);
                s2A[kt] = pack2(ax, ay);
                s2B[kt] = pack2(bx, by);
            }

            // ===== n8 tile A =====
            {
                const int tA = tb0 + r;
                uint32_t bh0 = xhb[cq * PX + tA];
                uint32_t bh1 = xhb[(cq + 4) * PX + tA];
                uint32_t bl0 = xlb[cq * PX + tA];
                uint32_t bl1 = xlb[(cq + 4) * PX + tA];
                float dG[KS][4] = {};
                #pragma unroll
                for (int kt = 0; kt < KS; kt++) {
                    mma_bf16(dG[kt], ah[kt], bh0, bh1);
                    mma_bf16(dG[kt], ah[kt], bl0, bl1);
                    mma_bf16(dG[kt], al[kt], bh0, bh1);
                }
                yA0 = 0ull; yA1 = 0ull;
                #pragma unroll
                for (int kt = 0; kt < KS; kt++) {
                    yA0 = fma2(pack2(dG[kt][0], dG[kt][1]), s2A[kt], yA0);
                    yA1 = fma2(pack2(dG[kt][2], dG[kt][3]), s2A[kt], yA1);
                }
            }
            // ===== n8 tile B =====
            {
                const int tB = tb1 + r;
                uint32_t bh0 = xhb[cq * PX + tB];
                uint32_t bh1 = xhb[(cq + 4) * PX + tB];
                uint32_t bl0 = xlb[cq * PX + tB];
                uint32_t bl1 = xlb[(cq + 4) * PX + tB];
                float dG[KS][4] = {};
                #pragma unroll
                for (int kt = 0; kt < KS; kt++) {
                    mma_bf16(dG[kt], ah[kt], bh0, bh1);
                    mma_bf16(dG[kt], ah[kt], bl0, bl1);
                    mma_bf16(dG[kt], al[kt], bh0, bh1);
                }
                yB0 = 0ull; yB1 = 0ull;
                #pragma unroll
                for (int kt = 0; kt < KS; kt++) {
                    yB0 = fma2(pack2(dG[kt][0], dG[kt][1]), s2B[kt], yB0);
                    yB1 = fma2(pack2(dG[kt][2], dG[kt][3]), s2B[kt], yB1);
                }
            }

            // ===== composed stores (R10 mapping) =====
            unsigned long long eA0 = __shfl_xor_sync(FULL, yA0, 1);
            unsigned long long eA1 = __shfl_xor_sync(FULL, yA1, 1);
            unsigned long long eB0 = __shfl_xor_sync(FULL, yB0, 1);
            unsigned long long eB1 = __shfl_xor_sync(FULL, yB1, 1);

            const int off = ((cq & 1) << 3) | ((cq >> 1) << 2);
            float4 v0, v1;
            if ((cq & 1) == 0) {
                v0 = make_float4(u64lo(yA0), u64hi(yA0), u64lo(eA0), u64hi(eA0));
                v1 = make_float4(u64lo(yA1), u64hi(yA1), u64lo(eA1), u64hi(eA1));
            } else {
                v0 = make_float4(u64lo(eB0), u64hi(eB0), u64lo(yB0), u64hi(yB0));
                v1 = make_float4(u64lo(eB1), u64hi(eB1), u64lo(yB1), u64hi(yB1));
            }
            *reinterpret_cast<float4*>(ob + (long long)r       * NN + tb0 + off) = v0;
            *reinterpret_cast<float4*>(ob + (long long)(r + 8) * NN + tb0 + off) = v1;
        }

        // rotate s double-buffer
        #pragma unroll
        for (int kt = 0; kt < KS; kt++) sv[kt] = sn[kt];
    }
}

extern "C" void kernel_launch(void* const* d_in, const int* in_sizes, int n_in,
                              void* d_out, int out_size)
{
    const float* inp = (const float*)d_in[0];   // input  [8,16,524288]
    const float* wgt = (const float*)d_in[1];   // weight [16,4,16]
    const float* att = (const float*)d_in[2];   // attention_score [8,4,524288]
    float* out = (float*)d_out;                 // [8,16,524288]

    tconv_mma_kernel<<<GRID, THREADS>>>(inp, wgt, att, out);
}

// round 14
// speedup vs baseline: 1.0614x; 1.0614x over previous
#include <cuda_runtime.h>
#include <cstdint>

namespace {
constexpr int  CIN  = 16;
constexpr int  COUT = 16;
constexpr int  KS   = 4;
constexpr long long NN = 524288;
constexpr int  THREADS = 128;                 // 4 warps
constexpr int  GRID    = 8192;
constexpr int  NWARPS  = GRID * 4;            // 32768 warps
constexpr int  NBLK    = (int)(8 * NN / 32);  // 131072 32-token blocks
constexpr int  PER_W   = NBLK / NWARPS;       // 4 blocks per warp
constexpr int  PXW     = 40;                  // xh/xl row pitch (banks 8p+lane)
constexpr int  PSW     = 36;                  // s row pitch (banks 4k+lane)
}

__device__ __forceinline__ unsigned long long fma2(unsigned long long a,
                                                   unsigned long long b,
                                                   unsigned long long c) {
    unsigned long long d;
    asm("fma.rn.f32x2 %0, %1, %2, %3;" : "=l"(d) : "l"(a), "l"(b), "l"(c));
    return d;
}
__device__ __forceinline__ unsigned long long pack2(float lo, float hi) {
    unsigned long long d;
    asm("mov.b64 %0, {%1, %2};" : "=l"(d) : "f"(lo), "f"(hi));
    return d;
}
// pack two f32 -> bf16x2 rn. First operand = HIGH half (element 1).
__device__ __forceinline__ uint32_t packbf(float hi, float lo) {
    uint32_t r;
    asm("cvt.rn.bf16x2.f32 %0, %1, %2;" : "=r"(r) : "f"(hi), "f"(lo));
    return r;
}
// m16n8k16 row.col bf16 MMA, accumulate in place. A = weights (regs).
__device__ __forceinline__ void mma_bf16(float* d, const uint32_t* a,
                                         uint32_t b0, uint32_t b1) {
    asm volatile(
        "mma.sync.aligned.m16n8k16.row.col.f32.bf16.bf16.f32 "
        "{%0,%1,%2,%3}, {%4,%5,%6,%7}, {%8,%9}, {%0,%1,%2,%3};"
        : "+f"(d[0]), "+f"(d[1]), "+f"(d[2]), "+f"(d[3])
        : "r"(a[0]), "r"(a[1]), "r"(a[2]), "r"(a[3]), "r"(b0), "r"(b1));
}
__device__ __forceinline__ float u64lo(unsigned long long v) {
    return __uint_as_float((uint32_t)v);
}
__device__ __forceinline__ float u64hi(unsigned long long v) {
    return __uint_as_float((uint32_t)(v >> 32));
}

__global__ __launch_bounds__(THREADS, 5)
void tconv_mma_kernel(const float* __restrict__ inp,   // [B, CIN, N]
                      const float* __restrict__ wgt,   // [COUT, KS, CIN]
                      const float* __restrict__ att,   // [B, KS, N]
                      float* __restrict__ out)         // [B, COUT, N]
{
    // Warp-PRIVATE staging (no CTA barriers anywhere in the main loop).
    // xh/xl: bf16x2 channel-pair rows [p][tok32]; ss: fp32 [k][tok32].
    __shared__ __align__(16) uint32_t xh[4][8 * PXW];
    __shared__ __align__(16) uint32_t xl[4][8 * PXW];
    __shared__ __align__(16) float    ssm[4][KS * PSW];

    const int tid  = threadIdx.x;
    const int lane = tid & 31;
    const int w    = tid >> 5;
    const int cq   = lane & 3;
    const int r    = lane >> 2;
    const unsigned FULL = 0xFFFFFFFFu;

    uint32_t* xhb = xh[w];
    uint32_t* xlb = xl[w];
    float*    sb  = ssm[w];

    // ---- W as A-fragments, built once (split hi/lo) — R11 verbatim ----
    uint32_t ah[KS][4], al[KS][4];
    #pragma unroll
    for (int kt = 0; kt < KS; kt++) {
        #pragma unroll
        for (int idx = 0; idx < 4; idx++) {
            int o  = r + 8 * (idx & 1);
            int cb = 2 * cq + 8 * (idx >> 1);
            float wa = wgt[(o * KS + kt) * CIN + cb];
            float wb = wgt[(o * KS + kt) * CIN + cb + 1];
            uint32_t hp = packbf(wb, wa);
            float ha = __uint_as_float(hp << 16);
            float hb = __uint_as_float(hp & 0xFFFF0000u);
            ah[kt][idx] = hp;
            al[kt][idx] = packbf(wb - hb, wa - ha);
        }
    }

    const int wg = blockIdx.x * 4 + w;            // global warp id

    // ---- prologue: load block 0 (lane = token) ----
    float xv[CIN], sv[KS];
    {
        int blk = wg;                              // + 0 * NWARPS
        long long b  = blk >> 14;                  // NN/32 = 16384
        long long n0 = ((long long)(blk & 16383)) << 5;
        #pragma unroll
        for (int c = 0; c < CIN; c++)
            xv[c] = inp[(b * CIN + c) * NN + n0 + lane];
        #pragma unroll
        for (int kt = 0; kt < KS; kt++)
            sv[kt] = att[(b * KS + kt) * NN + n0 + lane];
    }

    #pragma unroll 1
    for (int i = 0; i < PER_W; i++) {
        const int blk = wg + i * NWARPS;
        const long long b  = blk >> 14;
        const long long n0 = ((long long)(blk & 16383)) << 5;

        // ---- stage: split x to bf16 hi/lo, warp-private, conflict-free ----
        #pragma unroll
        for (int p = 0; p < 8; p++) {
            float x0 = xv[2 * p], x1 = xv[2 * p + 1];
            uint32_t hp = packbf(x1, x0);
            float f0 = __uint_as_float(hp << 16);
            float f1 = __uint_as_float(hp & 0xFFFF0000u);
            uint32_t lp = packbf(x1 - f1, x0 - f0);
            xhb[p * PXW + lane] = hp;
            xlb[p * PXW + lane] = lp;
        }
        #pragma unroll
        for (int kt = 0; kt < KS; kt++)
            sb[kt * PSW + lane] = sv[kt];

        // ---- prefetch block i+1 into the same registers ----
        if (i + 1 < PER_W) {
            int bn = wg + (i + 1) * NWARPS;
            long long bb = bn >> 14;
            long long nn = ((long long)(bn & 16383)) << 5;
            #pragma unroll
            for (int c = 0; c < CIN; c++)
                xv[c] = inp[(bb * CIN + c) * NN + nn + lane];
            #pragma unroll
            for (int kt = 0; kt < KS; kt++)
                sv[kt] = att[(bb * KS + kt) * NN + nn + lane];
        }
        __syncwarp();

        float* ob = out + b * COUT * NN + n0;

        #pragma unroll
        for (int jp = 0; jp < 2; jp++) {
            const int tb0 = jp * 16;
            unsigned long long yA0, yA1, yB0, yB1;

            // ===== n8 tile A (tokens tb0..tb0+7) =====
            {
                const int tA = tb0 + r;
                uint32_t bh0 = xhb[cq * PXW + tA];
                uint32_t bh1 = xhb[(cq + 4) * PXW + tA];
                uint32_t bl0 = xlb[cq * PXW + tA];
                uint32_t bl1 = xlb[(cq + 4) * PXW + tA];
                float dG[KS][4] = {};
                #pragma unroll
                for (int kt = 0; kt < KS; kt++) {
                    mma_bf16(dG[kt], ah[kt], bh0, bh1);
                    mma_bf16(dG[kt], ah[kt], bl0, bl1);
                    mma_bf16(dG[kt], al[kt], bh0, bh1);
                }
                yA0 = 0ull; yA1 = 0ull;
                #pragma unroll
                for (int kt = 0; kt < KS; kt++) {
                    unsigned long long s2 = *reinterpret_cast<const unsigned long long*>(
                        sb + kt * PSW + tb0 + 2 * cq);
                    yA0 = fma2(pack2(dG[kt][0], dG[kt][1]), s2, yA0);
                    yA1 = fma2(pack2(dG[kt][2], dG[kt][3]), s2, yA1);
                }
            }
            // ===== n8 tile B (tokens tb0+8..tb0+15) =====
            {
                const int tB = tb0 + 8 + r;
                uint32_t bh0 = xhb[cq * PXW + tB];
                uint32_t bh1 = xhb[(cq + 4) * PXW + tB];
                uint32_t bl0 = xlb[cq * PXW + tB];
                uint32_t bl1 = xlb[(cq + 4) * PXW + tB];
                float dG[KS][4] = {};
                #pragma unroll
                for (int kt = 0; kt < KS; kt++) {
                    mma_bf16(dG[kt], ah[kt], bh0, bh1);
                    mma_bf16(dG[kt], ah[kt], bl0, bl1);
                    mma_bf16(dG[kt], al[kt], bh0, bh1);
                }
                yB0 = 0ull; yB1 = 0ull;
                #pragma unroll
                for (int kt = 0; kt < KS; kt++) {
                    unsigned long long s2 = *reinterpret_cast<const unsigned long long*>(
                        sb + kt * PSW + tb0 + 8 + 2 * cq);
                    yB0 = fma2(pack2(dG[kt][0], dG[kt][1]), s2, yB0);
                    yB1 = fma2(pack2(dG[kt][2], dG[kt][3]), s2, yB1);
                }
            }

            // ===== composed stores (R10/R11 proven mapping) =====
            unsigned long long eA0 = __shfl_xor_sync(FULL, yA0, 1);
            unsigned long long eA1 = __shfl_xor_sync(FULL, yA1, 1);
            unsigned long long eB0 = __shfl_xor_sync(FULL, yB0, 1);
            unsigned long long eB1 = __shfl_xor_sync(FULL, yB1, 1);

            const int off = ((cq & 1) << 3) | ((cq >> 1) << 2);
            float4 v0, v1;
            if ((cq & 1) == 0) {
                v0 = make_float4(u64lo(yA0), u64hi(yA0), u64lo(eA0), u64hi(eA0));
                v1 = make_float4(u64lo(yA1), u64hi(yA1), u64lo(eA1), u64hi(eA1));
            } else {
                v0 = make_float4(u64lo(eB0), u64hi(eB0), u64lo(yB0), u64hi(yB0));
                v1 = make_float4(u64lo(eB1), u64hi(eB1), u64lo(yB1), u64hi(yB1));
            }
            *reinterpret_cast<float4*>(ob + (long long)r       * NN + tb0 + off) = v0;
            *reinterpret_cast<float4*>(ob + (long long)(r + 8) * NN + tb0 + off) = v1;
        }
        __syncwarp();   // order: this tile's LDS before next tile's STS overwrite
    }
}

extern "C" void kernel_launch(void* const* d_in, const int* in_sizes, int n_in,
                              void* d_out, int out_size)
{
    const float* inp = (const float*)d_in[0];   // input  [8,16,524288]
    const float* wgt = (const float*)d_in[1];   // weight [16,4,16]
    const float* att = (const float*)d_in[2];   // attention_score [8,4,524288]
    float* out = (float*)d_out;                 // [8,16,524288]

    tconv_mma_kernel<<<GRID, THREADS>>>(inp, wgt, att, out);
}